// round 12
// baseline (speedup 1.0000x reference)
#include <cuda_runtime.h>
#include <cstdint>

// ---------------------------------------------------------------------------
// AlignedMPNN: B=8, N=256, F=128, D=128
// Output: ret [8,256,128] followed by et [8,256,256,128]
// ---------------------------------------------------------------------------

#define Bq 8
#define Nn 256
#define Ff 128
#define Dd 128
#define M_ET (Bq * Nn * Nn)          // 524288
#define NROWS (Bq * (Nn + 1))        // 2056
#define N_TILES1 (M_ET / 128)        // 4096 tiles of 128 rows

// scratch for MPNN chain
__device__ float g_msg1[NROWS * Dd];
__device__ float g_msg2[NROWS * Dd];
__device__ float g_o1[NROWS * Dd];

// ===========================================================================
// helpers
// ===========================================================================
__device__ __forceinline__ uint32_t smem_u32_of(const void* p) {
    uint32_t a;
    asm("{ .reg .u64 t; cvta.to.shared.u64 t, %1; cvt.u32.u64 %0, t; }" : "=r"(a) : "l"(p));
    return a;
}

#define STS128(a0, a1, a2, a3, addr) \
    asm volatile("st.shared.v4.b32 [%0], {%1, %2, %3, %4};" :: "r"(addr), "r"(a0), "r"(a1), "r"(a2), "r"(a3) : "memory")

#define LDSM2(r, addr) \
    asm volatile("ldmatrix.sync.aligned.m8n8.x2.shared.b16 {%0,%1}, [%2];" \
        : "=r"((r)[0]), "=r"((r)[1]) : "r"(addr))

#define MMA_F16(d, a, b) \
    asm volatile("mma.sync.aligned.m16n8k16.row.col.f32.f16.f16.f32 " \
        "{%0,%1,%2,%3}, {%4,%5,%6,%7}, {%8,%9}, {%0,%1,%2,%3};" \
        : "+f"((d)[0]), "+f"((d)[1]), "+f"((d)[2]), "+f"((d)[3]) \
        : "r"((a)[0]), "r"((a)[1]), "r"((a)[2]), "r"((a)[3]), "r"((b)[0]), "r"((b)[1]))

// W f16 tile layout: 64B rows, unit u (0..3, 16B), XOR swizzle. (verified R6+)
#define ASWZ64(r, u) ((uint32_t)((r) * 64 + (((u) ^ (((r) >> 1) & 3)) * 16)))

// pack two f32 -> f16x2 (x0 in low half)
__device__ __forceinline__ uint32_t cvt2h(float x0, float x1) {
    uint32_t r;
    asm("cvt.rn.f16x2.f32 %0, %1, %2;" : "=r"(r) : "f"(x1), "f"(x0));
    return r;
}

// ===========================================================================
// et GEMM: C[M,128] = A1[M,128k] @ W[0:128,:] + A2[M,128k] @ W[128:256,:] + be
// fp16 single-term mma.sync. 296 persistent CTAs x 256 threads, 2 CTAs/SM.
// Warp grid 4(M) x 2(N): 32 rows x 64 cols per warp. M-tile 128, k16 steps.
//
// A path: NO shared memory for A; each thread LDG.128s exactly the f32 its
// own fragments need (k-permuted W layout makes fragment k contiguous),
// cvt -> f16x2 in registers. NO __syncthreads in the main loop.
// Two independent CTAs per SM interleave: one CTA's LDG stalls are covered
// by the other CTA's MMA issue (CTA-level latency hiding, zero reg cost).
//
// smem per CTA (66KB): [0..65536) W f16 (8 k32-chunks), [65536..66048) bias.
// ===========================================================================
#define OFF_BIAS 65536
#define SMEM_ET  66048

__global__ __launch_bounds__(256, 2)
void et_mma_kernel(const float* __restrict__ A1,
                   const float* __restrict__ A2,
                   const float* __restrict__ W,     // [256,128] f32
                   const float* __restrict__ bias,  // [128]
                   float* __restrict__ C)           // [M,128]
{
    extern __shared__ char smem[];
    const uint32_t sb = smem_u32_of(smem);
    const int tid   = threadIdx.x;
    const int lane  = tid & 31;
    const int wid   = tid >> 5;
    const int warpM = wid >> 1;      // 0..3 -> rows warpM*32
    const int warpN = wid & 1;       // 0..1 -> cols warpN*64

    // ---- one-time W conversion: frag-ordered (permuted) k layout ----
    {
        const int n = tid & 127;
        const int g = tid >> 7;                 // 0..1
#pragma unroll
        for (int t = 0; t < 16; ++t) {
            const int kk = g * 16 + t;          // 16B-unit index 0..31
            const int c  = kk >> 2;             // k32 chunk
            const int u  = kk & 3;
            float w[8];
#pragma unroll
            for (int j = 0; j < 8; ++j) {
                const int p   = (u & 1) * 8 + j;    // frag position in k16
                const int akl = (p < 8) ? ((p >> 1) * 4 + (p & 1))
                                        : (((p - 8) >> 1) * 4 + 2 + (p & 1));
                const int kact = c * 32 + (u >> 1) * 16 + akl;
                w[j] = W[kact * 128 + n];
            }
            uint32_t p0 = cvt2h(w[0], w[1]);
            uint32_t p1 = cvt2h(w[2], w[3]);
            uint32_t p2 = cvt2h(w[4], w[5]);
            uint32_t p3 = cvt2h(w[6], w[7]);
            STS128(p0, p1, p2, p3, sb + c * 8192 + ASWZ64(n, u));
        }
        if (tid < 128) ((float*)(smem + OFF_BIAS))[tid] = bias[tid];
    }
    __syncthreads();

    // ---- invariants ----
    const int ls = lane & 15;
    const int n0 = warpN * 64 + (ls & 7);
    const int ub = ls >> 3;
    const int xn = (n0 >> 1) & 3;
    uint32_t boffs[2];
#pragma unroll
    for (int s = 0; s < 2; ++s)
        boffs[s] = (uint32_t)(n0 * 64 + (((2 * s + ub) ^ xn) * 16));

    // A fragment addressing: rows rbase + mt*16 (+8), cols kbase + (lane&3)*4
    const int rbase = warpM * 32 + (lane >> 2);
    const int acol  = (lane & 3) << 2;
    const float* bias_s = (const float*)(smem + OFF_BIAS);

    int tile = blockIdx.x;

    // prefetch step (c=0, s=0) of first tile
    float4 pv[2][2];     // [mt][row half]
    if (tile < N_TILES1) {
#pragma unroll
        for (int mt = 0; mt < 2; ++mt) {
            const float* pr = A1 + (size_t)(tile * 128 + rbase + mt * 16) * 128 + acol;
            pv[mt][0] = *(const float4*)pr;
            pv[mt][1] = *(const float4*)(pr + 8 * 128);
        }
    }

    while (tile < N_TILES1) {
        float acc[2][8][4];
#pragma unroll
        for (int nt = 0; nt < 8; ++nt) {
            const float2 bb = *(const float2*)&bias_s[warpN * 64 + nt * 8 + (lane & 3) * 2];
#pragma unroll
            for (int mt = 0; mt < 2; ++mt) {
                acc[mt][nt][0] = bb.x; acc[mt][nt][1] = bb.y;
                acc[mt][nt][2] = bb.x; acc[mt][nt][3] = bb.y;
            }
        }

#pragma unroll 1
        for (int c = 0; c < 8; ++c) {
#pragma unroll
            for (int s = 0; s < 2; ++s) {
                // B fragments for this k16 step
                uint32_t Bv[8][2];
                const uint32_t wb = sb + (uint32_t)(c * 8192) + boffs[s];
#pragma unroll
                for (int nt = 0; nt < 8; ++nt) LDSM2(Bv[nt], wb + nt * 512);

                // next-step coordinates (wraps into next tile's step 0)
                int ntile = tile, nc = c, ns = s + 1;
                if (ns == 2) { ns = 0; if (++nc == 8) { nc = 0; ntile += gridDim.x; } }
                const float* nbase = (nc < 4) ? A1 : A2;
                const int    ncol  = (nc & 3) * 32 + ns * 16 + acol;
                const bool   valid = ntile < N_TILES1;

                // mt = 0: convert, refill prefetch, MMA
                {
                    uint32_t Af[4];
                    Af[0] = cvt2h(pv[0][0].x, pv[0][0].y);
                    Af[1] = cvt2h(pv[0][1].x, pv[0][1].y);
                    Af[2] = cvt2h(pv[0][0].z, pv[0][0].w);
                    Af[3] = cvt2h(pv[0][1].z, pv[0][1].w);
                    if (valid) {
                        const float* pr = nbase + (size_t)(ntile * 128 + rbase) * 128 + ncol;
                        pv[0][0] = *(const float4*)pr;
                        pv[0][1] = *(const float4*)(pr + 8 * 128);
                    }
#pragma unroll
                    for (int nt = 0; nt < 8; ++nt) MMA_F16(acc[0][nt], Af, Bv[nt]);
                }
                // mt = 1
                {
                    uint32_t Af[4];
                    Af[0] = cvt2h(pv[1][0].x, pv[1][0].y);
                    Af[1] = cvt2h(pv[1][1].x, pv[1][1].y);
                    Af[2] = cvt2h(pv[1][0].z, pv[1][0].w);
                    Af[3] = cvt2h(pv[1][1].z, pv[1][1].w);
                    if (valid) {
                        const float* pr = nbase + (size_t)(ntile * 128 + rbase + 16) * 128 + ncol;
                        pv[1][0] = *(const float4*)pr;
                        pv[1][1] = *(const float4*)(pr + 8 * 128);
                    }
#pragma unroll
                    for (int nt = 0; nt < 8; ++nt) MMA_F16(acc[1][nt], Af, Bv[nt]);
                }
            }
        }

        // epilogue: direct STG (32B-sector aligned float2 stores); no barrier
        const size_t m0 = (size_t)tile * 128;
#pragma unroll
        for (int mt = 0; mt < 2; ++mt) {
            const size_t r0 = m0 + warpM * 32 + mt * 16 + (lane >> 2);
#pragma unroll
            for (int nt = 0; nt < 8; ++nt) {
                const int col = warpN * 64 + nt * 8 + (lane & 3) * 2;
                *(float2*)&C[r0 * 128 + col]       = make_float2(acc[mt][nt][0], acc[mt][nt][1]);
                *(float2*)&C[(r0 + 8) * 128 + col] = make_float2(acc[mt][nt][2], acc[mt][nt][3]);
            }
        }
        tile += gridDim.x;
    }
}

// ===========================================================================
// Kernel 2: msg1/msg2/o1 = nt @ {W_m1,W_m2,W_o1} + bias.
// ===========================================================================
__global__ __launch_bounds__(512)
void msgs_gemm_kernel(const float* __restrict__ node,
                      const float* __restrict__ hidden,
                      const float* __restrict__ Wm1, const float* __restrict__ bm1,
                      const float* __restrict__ Wm2, const float* __restrict__ bm2,
                      const float* __restrict__ Wo1, const float* __restrict__ bo1)
{
    __shared__ float s[8][2 * Ff];
    __shared__ float part[3][3][8][128];
    const int r0  = blockIdx.x * 8;
    const int tid = threadIdx.x;
    const int col = tid & 127;
    const int kq  = tid >> 7;

    for (int t = tid; t < 8 * 256; t += 512) {
        const int r = t >> 8, k = t & 255;
        const int rowi = r0 + r;
        const int b = rowi / (Nn + 1);
        const int i = rowi % (Nn + 1);
        float v = 0.f;
        if (i < Nn)
            v = (k < Ff) ? node[(b * Nn + i) * Ff + k]
                         : hidden[(b * Nn + i) * Ff + (k - Ff)];
        s[r][k] = v;
    }
    __syncthreads();

    float a1[8], a2[8], a3[8];
#pragma unroll
    for (int r = 0; r < 8; ++r) { a1[r] = 0.f; a2[r] = 0.f; a3[r] = 0.f; }

    const int kbase = kq * 64;
#pragma unroll 4
    for (int kk = 0; kk < 64; ++kk) {
        const int k = kbase + kk;
        const float w1 = Wm1[k * Dd + col];
        const float w2 = Wm2[k * Dd + col];
        const float w3 = Wo1[k * Dd + col];
#pragma unroll
        for (int r = 0; r < 8; ++r) {
            const float sv = s[r][k];
            a1[r] = fmaf(sv, w1, a1[r]);
            a2[r] = fmaf(sv, w2, a2[r]);
            a3[r] = fmaf(sv, w3, a3[r]);
        }
    }

    if (kq) {
#pragma unroll
        for (int r = 0; r < 8; ++r) {
            part[kq - 1][0][r][col] = a1[r];
            part[kq - 1][1][r][col] = a2[r];
            part[kq - 1][2][r][col] = a3[r];
        }
    }
    __syncthreads();

    if (kq == 0) {
        const float bb1 = bm1[col], bb2 = bm2[col], bb3 = bo1[col];
#pragma unroll
        for (int r = 0; r < 8; ++r) {
            float o1 = a1[r] + bb1, o2 = a2[r] + bb2, o3 = a3[r] + bb3;
#pragma unroll
            for (int q = 0; q < 3; ++q) {
                o1 += part[q][0][r][col];
                o2 += part[q][1][r][col];
                o3 += part[q][2][r][col];
            }
            const int rowi = r0 + r;
            g_msg1[rowi * Dd + col] = o1;
            g_msg2[rowi * Dd + col] = o2;
            g_o1[rowi * Dd + col]   = o3;
        }
    }
}

// ===========================================================================
// Kernel 3 (fused): masked max + add msg1, then ret = o1 + msgs @ W_o2 + b_o2
// ===========================================================================
__global__ __launch_bounds__(256)
void maxfinal_kernel(const int* __restrict__ adj,
                     const float* __restrict__ Wo2,
                     const float* __restrict__ bo2,
                     float* __restrict__ out)      // [B*N,128]
{
    __shared__ int mask[Nn];
    __shared__ float red[2][4][128];
    __shared__ float ms[4][128];
    __shared__ float pg[4][128];
    const int blk = blockIdx.x;
    const int b   = blk >> 6;
    const int j0  = (blk & 63) * 4;
    const int tid = threadIdx.x;
    const int d   = tid & 127;
    const int ih  = tid >> 7;

    {
        const int* p = adj + ((size_t)(b * Nn + tid) * Nn + j0);
        const int4 a = *(const int4*)p;
        mask[tid] = (a.x > 0) | ((a.y > 0) << 1) | ((a.z > 0) << 2) | ((a.w > 0) << 3);
    }
    __syncthreads();

    const float* m2 = g_msg2 + (size_t)(b * (Nn + 1)) * Dd + d;
    const float vv = m2[Nn * Dd];
    float vj[4] = {vv, vv, vv, vv};

#pragma unroll 4
    for (int ii = 0; ii < 128; ++ii) {
        const int i = ih * 128 + ii;
        const float x = m2[i * Dd];
        const int mk = mask[i];
#pragma unroll
        for (int q = 0; q < 4; ++q)
            if (mk & (1 << q)) vj[q] = fmaxf(vj[q], x);
    }
#pragma unroll
    for (int q = 0; q < 4; ++q) red[ih][q][d] = vj[q];
    __syncthreads();

    if (ih == 0) {
#pragma unroll
        for (int q = 0; q < 4; ++q)
            ms[q][d] = g_msg1[(size_t)(b * (Nn + 1) + j0 + q) * Dd + d]
                     + fmaxf(red[0][q][d], red[1][q][d]);
    }
    __syncthreads();

    float acc[4] = {0.f, 0.f, 0.f, 0.f};
    const int kb = ih * 64;
#pragma unroll 4
    for (int kk = 0; kk < 64; ++kk) {
        const int k = kb + kk;
        const float w = Wo2[k * Dd + d];
#pragma unroll
        for (int q = 0; q < 4; ++q) acc[q] = fmaf(ms[q][k], w, acc[q]);
    }
    if (ih) {
#pragma unroll
        for (int q = 0; q < 4; ++q) pg[q][d] = acc[q];
    }
    __syncthreads();
    if (!ih) {
        const float bb = bo2[d];
#pragma unroll
        for (int q = 0; q < 4; ++q)
            out[(size_t)(b * Nn + j0 + q) * Dd + d] =
                acc[q] + pg[q][d] + g_o1[(size_t)(b * (Nn + 1) + j0 + q) * Dd + d] + bb;
    }
}

// ===========================================================================
extern "C" void kernel_launch(void* const* d_in, const int* in_sizes, int n_in,
                              void* d_out, int out_size)
{
    const float* node_fts = (const float*)d_in[0];
    const float* edge_fts = (const float*)d_in[1];
    const int*   adj_mat  = (const int*)d_in[3];
    const float* hidden   = (const float*)d_in[4];
    const float* e_hidden = (const float*)d_in[5];
    const float* We   = (const float*)d_in[6];
    const float* be   = (const float*)d_in[7];
    const float* W_m1 = (const float*)d_in[8];
    const float* b_m1 = (const float*)d_in[9];
    const float* W_m2 = (const float*)d_in[10];
    const float* b_m2 = (const float*)d_in[11];
    const float* W_o1 = (const float*)d_in[12];
    const float* b_o1 = (const float*)d_in[13];
    const float* W_o2 = (const float*)d_in[14];
    const float* b_o2 = (const float*)d_in[15];

    float* ret_out = (float*)d_out;
    float* et_out  = (float*)d_out + Bq * Nn * Dd;

    static cudaStream_t s_chain = nullptr;
    static cudaEvent_t ev_fork = nullptr, ev_join = nullptr;
    if (!s_chain) {
        cudaStreamCreateWithFlags(&s_chain, cudaStreamNonBlocking);
        cudaEventCreateWithFlags(&ev_fork, cudaEventDisableTiming);
        cudaEventCreateWithFlags(&ev_join, cudaEventDisableTiming);
        cudaFuncSetAttribute(et_mma_kernel, cudaFuncAttributeMaxDynamicSharedMemorySize, SMEM_ET);
    }

    // fork: MPNN chain runs concurrently with the big et GEMM
    cudaEventRecord(ev_fork, 0);
    cudaStreamWaitEvent(s_chain, ev_fork, 0);
    msgs_gemm_kernel<<<NROWS / 8, 512, 0, s_chain>>>(node_fts, hidden,
                                                     W_m1, b_m1, W_m2, b_m2, W_o1, b_o1);
    maxfinal_kernel<<<Bq * Nn / 4, 256, 0, s_chain>>>(adj_mat, W_o2, b_o2, ret_out);
    cudaEventRecord(ev_join, s_chain);

    // et GEMM (barrier-free A-in-register fp16 mma, 2 independent CTAs/SM)
    et_mma_kernel<<<296, 256, SMEM_ET>>>(edge_fts, e_hidden, We, be, et_out);

    // join
    cudaStreamWaitEvent(0, ev_join, 0);
}